// round 1
// baseline (speedup 1.0000x reference)
#include <cuda_runtime.h>
#include <cstdint>

#define BB 32
#define LL 1024
#define HH 128

// Scratch (allocation-free rule: __device__ globals)
__device__ float g_E[(size_t)BB * LL * LL];   // exp(masked scores), 128 MB
__device__ float g_R[BB * LL];                // row sums (over m)
__device__ float g_C[BB * LL];                // col sums (over l)

// ---------------------------------------------------------------------------
// K1: E[b,l,m] = mask ? exp(temp * dot(a[b,l,:], b[b,m,:])) : 0
// 128x128 output tile per block, 256 threads, 8x8 per thread, K-chunks of 16,
// k-major transposed smem so inner loop is LDS.128 + FFMA.
// ---------------------------------------------------------------------------
__global__ __launch_bounds__(256) void k1_scores(
    const float* __restrict__ a, const float* __restrict__ b,
    const int* __restrict__ ma, const int* __restrict__ mb,
    const float* __restrict__ tptr)
{
    const int batch = blockIdx.z;
    const int tl = blockIdx.y * 128;
    const int tm = blockIdx.x * 128;
    const int t  = threadIdx.x;
    const int tx = t & 15, ty = t >> 4;

    __shared__ float As[16][132];
    __shared__ float Bs[16][132];

    float acc[8][8];
#pragma unroll
    for (int i = 0; i < 8; i++)
#pragma unroll
        for (int j = 0; j < 8; j++) acc[i][j] = 0.f;

    const float* abase = a + (size_t)(batch * LL + tl) * HH;
    const float* bbase = b + (size_t)(batch * LL + tm) * HH;
    const int kq = t & 3;       // which float4 along k
    const int l0 = t >> 2;      // 0..63

    for (int kc = 0; kc < HH; kc += 16) {
        __syncthreads();
#pragma unroll
        for (int h = 0; h < 2; h++) {
            const int l = l0 + h * 64;
            float4 va = *(const float4*)(abase + (size_t)l * HH + kc + kq * 4);
            float4 vb = *(const float4*)(bbase + (size_t)l * HH + kc + kq * 4);
            As[kq * 4 + 0][l] = va.x; As[kq * 4 + 1][l] = va.y;
            As[kq * 4 + 2][l] = va.z; As[kq * 4 + 3][l] = va.w;
            Bs[kq * 4 + 0][l] = vb.x; Bs[kq * 4 + 1][l] = vb.y;
            Bs[kq * 4 + 2][l] = vb.z; Bs[kq * 4 + 3][l] = vb.w;
        }
        __syncthreads();
#pragma unroll
        for (int k = 0; k < 16; k++) {
            float4 a0 = *(const float4*)&As[k][4 * ty];
            float4 a1 = *(const float4*)&As[k][64 + 4 * ty];
            float4 b0 = *(const float4*)&Bs[k][4 * tx];
            float4 b1 = *(const float4*)&Bs[k][64 + 4 * tx];
            float ar[8] = {a0.x, a0.y, a0.z, a0.w, a1.x, a1.y, a1.z, a1.w};
            float br[8] = {b0.x, b0.y, b0.z, b0.w, b1.x, b1.y, b1.z, b1.w};
#pragma unroll
            for (int i = 0; i < 8; i++)
#pragma unroll
                for (int j = 0; j < 8; j++)
                    acc[i][j] = fmaf(ar[i], br[j], acc[i][j]);
        }
    }

    const float temp = *tptr;
    int rm[8], cm[8];
#pragma unroll
    for (int i = 0; i < 8; i++) {
        const int r = (i < 4) ? (4 * ty + i) : (64 + 4 * ty + (i - 4));
        const int c = (i < 4) ? (4 * tx + i) : (64 + 4 * tx + (i - 4));
        rm[i] = ma[batch * LL + tl + r];
        cm[i] = mb[batch * LL + tm + c];
    }
#pragma unroll
    for (int i = 0; i < 8; i++) {
        const int r = (i < 4) ? (4 * ty + i) : (64 + 4 * ty + (i - 4));
        float* erow = g_E + (size_t)(batch * LL + tl + r) * LL + tm;
        float4 v0, v1;
        v0.x = (rm[i] && cm[0]) ? __expf(acc[i][0] * temp) : 0.f;
        v0.y = (rm[i] && cm[1]) ? __expf(acc[i][1] * temp) : 0.f;
        v0.z = (rm[i] && cm[2]) ? __expf(acc[i][2] * temp) : 0.f;
        v0.w = (rm[i] && cm[3]) ? __expf(acc[i][3] * temp) : 0.f;
        v1.x = (rm[i] && cm[4]) ? __expf(acc[i][4] * temp) : 0.f;
        v1.y = (rm[i] && cm[5]) ? __expf(acc[i][5] * temp) : 0.f;
        v1.z = (rm[i] && cm[6]) ? __expf(acc[i][6] * temp) : 0.f;
        v1.w = (rm[i] && cm[7]) ? __expf(acc[i][7] * temp) : 0.f;
        *(float4*)(erow + 4 * tx)      = v0;
        *(float4*)(erow + 64 + 4 * tx) = v1;
    }
}

// ---------------------------------------------------------------------------
// K2a: row sums R[b,l] = sum_m E[b,l,m]. One block per row.
// ---------------------------------------------------------------------------
__global__ __launch_bounds__(256) void k2_row()
{
    const int row = blockIdx.x;            // 0..B*L-1
    const int t = threadIdx.x;
    float4 v = *(const float4*)(g_E + (size_t)row * LL + t * 4);
    float s = v.x + v.y + v.z + v.w;
    __shared__ float red[256];
    red[t] = s;
    __syncthreads();
    for (int o = 128; o > 0; o >>= 1) {
        if (t < o) red[t] += red[t + o];
        __syncthreads();
    }
    if (t == 0) g_R[row] = red[0];
}

// ---------------------------------------------------------------------------
// K2b: col sums C[b,m] = sum_l E[b,l,m]. Thread owns one column, coalesced.
// ---------------------------------------------------------------------------
__global__ __launch_bounds__(256) void k2_col()
{
    const int batch = blockIdx.y;
    const int m = blockIdx.x * 256 + threadIdx.x;
    const float* base = g_E + (size_t)batch * LL * LL + m;
    float s0 = 0.f, s1 = 0.f, s2 = 0.f, s3 = 0.f;
#pragma unroll 4
    for (int l = 0; l < LL; l += 4) {
        s0 += base[(size_t)(l + 0) * LL];
        s1 += base[(size_t)(l + 1) * LL];
        s2 += base[(size_t)(l + 2) * LL];
        s3 += base[(size_t)(l + 3) * LL];
    }
    g_C[batch * LL + m] = (s0 + s1) + (s2 + s3);
}

// ---------------------------------------------------------------------------
// K3: feature_a[l,d] = sum_m (E/R or uniform) * b[m,d]
//     feature_b[l,d] = sum_m (E/C or uniform) * a[m,d]
// 64(l) x 128(d) dual-output tile per block, m-chunks of 16.
// ---------------------------------------------------------------------------
__global__ __launch_bounds__(256) void k3_features(
    const float* __restrict__ a, const float* __restrict__ b,
    float* __restrict__ out)
{
    const int batch = blockIdx.y;
    const int tl = blockIdx.x * 64;
    const int t  = threadIdx.x;
    const int tx = t & 15, ty = t >> 4;

    __shared__ float Wr[16][132];
    __shared__ float Wc[16][132];
    __shared__ float Ash[16][132];
    __shared__ float Bsh[16][132];

    float acc_a[4][8], acc_b[4][8];
#pragma unroll
    for (int i = 0; i < 4; i++)
#pragma unroll
        for (int j = 0; j < 8; j++) { acc_a[i][j] = 0.f; acc_b[i][j] = 0.f; }

    const int kq = t & 3;     // f4 group within m-chunk
    const int le = t >> 2;    // 0..63 : which l-row this thread loads/transforms
    const float rval = g_R[batch * LL + tl + le];
    const float invR = (rval > 0.f) ? (1.f / rval) : 0.f;
    const float addR = (rval > 0.f) ? 0.f : (1.f / 1024.f);
    const float* Ebase = g_E + (size_t)(batch * LL + tl + le) * LL;
    const float* Cbase = g_C + batch * LL;
    const float* arow = a + (size_t)batch * LL * HH;
    const float* brow = b + (size_t)batch * LL * HH;

    for (int mc = 0; mc < LL; mc += 16) {
        __syncthreads();
        // load a/b chunks [16 m][128 d], natural layout
#pragma unroll
        for (int h = 0; h < 2; h++) {
            const int mrow = (t >> 5) + h * 8;
            const int f4i = t & 31;
            *(float4*)&Bsh[mrow][f4i * 4] =
                *(const float4*)(brow + (size_t)(mc + mrow) * HH + f4i * 4);
            *(float4*)&Ash[mrow][f4i * 4] =
                *(const float4*)(arow + (size_t)(mc + mrow) * HH + f4i * 4);
        }
        // load E chunk for row le, transform to both weight tiles (m-major)
        float4 ev = *(const float4*)(Ebase + mc + kq * 4);
        float e4[4] = {ev.x, ev.y, ev.z, ev.w};
#pragma unroll
        for (int i = 0; i < 4; i++) {
            const int ml = kq * 4 + i;
            const float cval = Cbase[mc + ml];
            const float invC = (cval > 0.f) ? (1.f / cval) : 0.f;
            const float addC = (cval > 0.f) ? 0.f : (1.f / 1024.f);
            Wr[ml][le] = fmaf(e4[i], invR, addR);
            Wc[ml][le] = fmaf(e4[i], invC, addC);
        }
        __syncthreads();
#pragma unroll
        for (int k = 0; k < 16; k++) {
            float4 wr = *(const float4*)&Wr[k][4 * ty];
            float4 wc = *(const float4*)&Wc[k][4 * ty];
            float4 b0 = *(const float4*)&Bsh[k][4 * tx];
            float4 b1 = *(const float4*)&Bsh[k][64 + 4 * tx];
            float4 a0 = *(const float4*)&Ash[k][4 * tx];
            float4 a1 = *(const float4*)&Ash[k][64 + 4 * tx];
            float wrr[4] = {wr.x, wr.y, wr.z, wr.w};
            float wcc[4] = {wc.x, wc.y, wc.z, wc.w};
            float bv[8] = {b0.x, b0.y, b0.z, b0.w, b1.x, b1.y, b1.z, b1.w};
            float av[8] = {a0.x, a0.y, a0.z, a0.w, a1.x, a1.y, a1.z, a1.w};
#pragma unroll
            for (int i = 0; i < 4; i++)
#pragma unroll
                for (int j = 0; j < 8; j++) {
                    acc_a[i][j] = fmaf(wrr[i], bv[j], acc_a[i][j]);
                    acc_b[i][j] = fmaf(wcc[i], av[j], acc_b[i][j]);
                }
        }
    }

    const size_t FB = (size_t)BB * LL * HH;   // offset of feature_b
#pragma unroll
    for (int i = 0; i < 4; i++) {
        const int r = tl + 4 * ty + i;
        float* oa = out + (size_t)(batch * LL + r) * HH;
        float* ob = oa + FB;
        float4 va0 = {acc_a[i][0], acc_a[i][1], acc_a[i][2], acc_a[i][3]};
        float4 va1 = {acc_a[i][4], acc_a[i][5], acc_a[i][6], acc_a[i][7]};
        float4 vb0 = {acc_b[i][0], acc_b[i][1], acc_b[i][2], acc_b[i][3]};
        float4 vb1 = {acc_b[i][4], acc_b[i][5], acc_b[i][6], acc_b[i][7]};
        *(float4*)(oa + 4 * tx)      = va0;
        *(float4*)(oa + 64 + 4 * tx) = va1;
        *(float4*)(ob + 4 * tx)      = vb0;
        *(float4*)(ob + 64 + 4 * tx) = vb1;
    }
}

extern "C" void kernel_launch(void* const* d_in, const int* in_sizes, int n_in,
                              void* d_out, int out_size)
{
    const float* a    = (const float*)d_in[0];
    const float* b    = (const float*)d_in[1];
    const int*   ma   = (const int*)d_in[2];
    const int*   mb   = (const int*)d_in[3];
    const float* temp = (const float*)d_in[4];
    float* out = (float*)d_out;

    k1_scores<<<dim3(8, 8, BB), 256>>>(a, b, ma, mb, temp);
    k2_row<<<BB * LL, 256>>>();
    k2_col<<<dim3(LL / 256, BB), 256>>>();
    k3_features<<<dim3(LL / 64, BB), 256>>>(a, b, out);
}

// round 3
// speedup vs baseline: 2.1200x; 2.1200x over previous
#include <cuda_runtime.h>
#include <cuda_fp16.h>
#include <cstdint>

#define BB 32
#define LL 1024
#define HH 128
#define SK 136          // smem row stride in halfs (4-bank shift/row -> conflict-free ldmatrix)

// ---------------- scratch (__device__ globals; no allocs allowed) ----------
__device__ __half g_E16[(size_t)BB * LL * LL];   // exp(masked scores), 64 MB
__device__ __half g_a16[(size_t)BB * LL * HH];   // fp16 a, natural [b,l,h]
__device__ __half g_b16[(size_t)BB * LL * HH];   // fp16 b, natural [b,m,h]
__device__ __half g_b16T[(size_t)BB * HH * LL];  // fp16 b transposed [b,d,m]
__device__ __half g_a16T[(size_t)BB * HH * LL];  // fp16 a*invC transposed [b,d,m]
__device__ float  g_R[BB * LL];                  // row sums of E
__device__ float  g_C[BB * LL];                  // col sums of E
__device__ float  g_meanb[BB * HH];              // sum_m b[m,d]
__device__ float  g_vmask[BB * HH];              // sum_{m: C=0} a[m,d]

// ---------------- PTX helpers ----------------------------------------------
__device__ __forceinline__ uint32_t smem_u32(const void* p) {
    uint32_t a;
    asm("{ .reg .u64 t; cvta.to.shared.u64 t, %1; cvt.u32.u64 %0, t; }"
        : "=r"(a) : "l"(p));
    return a;
}
#define LDSM4(R0, R1, R2, R3, ADDR)                                            \
    asm volatile("ldmatrix.sync.aligned.m8n8.x4.shared.b16 {%0,%1,%2,%3}, [%4];" \
                 : "=r"(R0), "=r"(R1), "=r"(R2), "=r"(R3) : "r"(ADDR))

__device__ __forceinline__ void mma_16816(float* c, const uint32_t* a,
                                          uint32_t b0, uint32_t b1) {
    asm volatile(
        "mma.sync.aligned.m16n8k16.row.col.f32.f16.f16.f32 "
        "{%0,%1,%2,%3},{%4,%5,%6,%7},{%8,%9},{%0,%1,%2,%3};"
        : "+f"(c[0]), "+f"(c[1]), "+f"(c[2]), "+f"(c[3])
        : "r"(a[0]), "r"(a[1]), "r"(a[2]), "r"(a[3]), "r"(b0), "r"(b1));
}

// ---------------- prep: fp32 -> fp16 conversions ---------------------------
__global__ __launch_bounds__(256) void conv_ab(const float* __restrict__ a,
                                               const float* __restrict__ b) {
    size_t idx = (size_t)blockIdx.x * 256 + threadIdx.x;   // float4 index
    float4 va = ((const float4*)a)[idx];
    float4 vb = ((const float4*)b)[idx];
    uint2 pa, pb;
    ((__half2*)&pa)[0] = __floats2half2_rn(va.x, va.y);
    ((__half2*)&pa)[1] = __floats2half2_rn(va.z, va.w);
    ((__half2*)&pb)[0] = __floats2half2_rn(vb.x, vb.y);
    ((__half2*)&pb)[1] = __floats2half2_rn(vb.z, vb.w);
    ((uint2*)g_a16)[idx] = pa;
    ((uint2*)g_b16)[idx] = pb;
}

__global__ __launch_bounds__(256) void transpose_b(const float* __restrict__ b) {
    __shared__ __half tt[128][136];
    const int mt = blockIdx.x * 128, batch = blockIdx.y;
    const int t = threadIdx.x;
    const int r = t >> 1, dh = (t & 1) * 64;
    const float* src = b + ((size_t)(batch * LL + mt + r)) * HH + dh;
#pragma unroll
    for (int j = 0; j < 16; j++) {
        float4 v = *(const float4*)(src + j * 4);
        tt[dh + j * 4 + 0][r] = __float2half(v.x);
        tt[dh + j * 4 + 1][r] = __float2half(v.y);
        tt[dh + j * 4 + 2][r] = __float2half(v.z);
        tt[dh + j * 4 + 3][r] = __float2half(v.w);
    }
    __syncthreads();
    const int d = t >> 1, mh = (t & 1) * 64;
    uint4* dst = (uint4*)(g_b16T + ((size_t)(batch * HH + d)) * LL + mt + mh);
    const uint4* srow = (const uint4*)&tt[d][mh];
#pragma unroll
    for (int q = 0; q < 8; q++) dst[q] = srow[q];
}

// a16T[d][m] = a[m][d] * (C[m]>0 ? 1/C[m] : 0)
__global__ __launch_bounds__(256) void prep_fb(const float* __restrict__ a) {
    __shared__ __half tt[128][136];
    const int mt = blockIdx.x * 128, batch = blockIdx.y;
    const int t = threadIdx.x;
    const int r = t >> 1, dh = (t & 1) * 64;
    const float cv = g_C[batch * LL + mt + r];
    const float w = (cv > 0.f) ? (1.f / cv) : 0.f;
    const float* src = a + ((size_t)(batch * LL + mt + r)) * HH + dh;
#pragma unroll
    for (int j = 0; j < 16; j++) {
        float4 v = *(const float4*)(src + j * 4);
        tt[dh + j * 4 + 0][r] = __float2half(v.x * w);
        tt[dh + j * 4 + 1][r] = __float2half(v.y * w);
        tt[dh + j * 4 + 2][r] = __float2half(v.z * w);
        tt[dh + j * 4 + 3][r] = __float2half(v.w * w);
    }
    __syncthreads();
    const int d = t >> 1, mh = (t & 1) * 64;
    uint4* dst = (uint4*)(g_a16T + ((size_t)(batch * HH + d)) * LL + mt + mh);
    const uint4* srow = (const uint4*)&tt[d][mh];
#pragma unroll
    for (int q = 0; q < 8; q++) dst[q] = srow[q];
}

// meanb[d] = sum_m b[m,d] ; vmask[d] = sum_{m: C[m]==0} a[m,d]
__global__ __launch_bounds__(256) void meanb_vmask() {
    __shared__ float pb[2][128], pv[2][128];
    const int batch = blockIdx.x;
    const int d = threadIdx.x & 127, mh = threadIdx.x >> 7;
    const __half* bp = g_b16 + (size_t)batch * LL * HH + (size_t)mh * 512 * HH + d;
    const __half* ap = g_a16 + (size_t)batch * LL * HH + (size_t)mh * 512 * HH + d;
    const float* cp = g_C + batch * LL + mh * 512;
    float sb = 0.f, sv = 0.f;
#pragma unroll 8
    for (int m = 0; m < 512; m++) {
        sb += __half2float(bp[(size_t)m * HH]);
        float cv = cp[m];
        float av = __half2float(ap[(size_t)m * HH]);
        sv += (cv > 0.f) ? 0.f : av;
    }
    pb[mh][d] = sb;
    pv[mh][d] = sv;
    __syncthreads();
    if (threadIdx.x < 128) {
        g_meanb[batch * HH + threadIdx.x] = pb[0][threadIdx.x] + pb[1][threadIdx.x];
        g_vmask[batch * HH + threadIdx.x] = pv[0][threadIdx.x] + pv[1][threadIdx.x];
    }
}

// ---------------- K1: HMMA scores + mask + exp -----------------------------
__global__ __launch_bounds__(256) void k1_scores(const int* __restrict__ ma,
                                                 const int* __restrict__ mb,
                                                 const float* __restrict__ tptr) {
    extern __shared__ char dsm[];
    __half* As = (__half*)dsm;            // 128 x SK
    __half* Bs = As + 128 * SK;           // 128 x SK
    int* cms = (int*)(Bs + 128 * SK);     // 128 ints

    const int batch = blockIdx.z, l0 = blockIdx.y * 128, m0 = blockIdx.x * 128;
    const int t = threadIdx.x, lane = t & 31, w = t >> 5;
    const int wr = w >> 2, wc = w & 3;

    if (t < 128) cms[t] = mb[batch * LL + m0 + t];
    {
        const int row = t >> 1, kh = (t & 1) * 64;
        const uint4* asrc = (const uint4*)(g_a16 + ((size_t)(batch * LL + l0 + row)) * HH + kh);
        const uint4* bsrc = (const uint4*)(g_b16 + ((size_t)(batch * LL + m0 + row)) * HH + kh);
        uint4* adst = (uint4*)(As + row * SK + kh);
        uint4* bdst = (uint4*)(Bs + row * SK + kh);
#pragma unroll
        for (int j = 0; j < 8; j++) { adst[j] = asrc[j]; bdst[j] = bsrc[j]; }
    }
    __syncthreads();

    float acc[4][4][4];
#pragma unroll
    for (int i = 0; i < 4; i++)
#pragma unroll
        for (int j = 0; j < 4; j++)
#pragma unroll
            for (int k = 0; k < 4; k++) acc[i][j][k] = 0.f;

    const uint32_t aaddr = smem_u32(As) + ((wr * 64 + (lane & 15)) * SK + (lane >> 4) * 8) * 2;
    const uint32_t baddr = smem_u32(Bs) + ((wc * 32 + (lane & 15)) * SK + (lane >> 4) * 8) * 2;
#pragma unroll
    for (int c = 0; c < 8; c++) {
        uint32_t av[4][4], bv[2][4];
#pragma unroll
        for (int mi = 0; mi < 4; mi++)
            LDSM4(av[mi][0], av[mi][1], av[mi][2], av[mi][3],
                  aaddr + (mi * 16 * SK + c * 16) * 2);
#pragma unroll
        for (int nh = 0; nh < 2; nh++)
            LDSM4(bv[nh][0], bv[nh][1], bv[nh][2], bv[nh][3],
                  baddr + (nh * 16 * SK + c * 16) * 2);
#pragma unroll
        for (int mi = 0; mi < 4; mi++)
#pragma unroll
            for (int nj = 0; nj < 4; nj++)
                mma_16816(acc[mi][nj], av[mi], bv[nj >> 1][nj & 1], bv[nj >> 1][(nj & 1) + 2]);
    }

    const float temp = *tptr;
#pragma unroll
    for (int mi = 0; mi < 4; mi++) {
        const int r0 = wr * 64 + mi * 16 + (lane >> 2);
        const int gr0 = batch * LL + l0 + r0;
        const int rm0 = ma[gr0], rm1 = ma[gr0 + 8];
        __half* e0 = g_E16 + (size_t)gr0 * LL + m0;
#pragma unroll
        for (int nj = 0; nj < 4; nj++) {
            const int col = wc * 32 + nj * 8 + (lane & 3) * 2;
            const int cm0 = cms[col], cm1 = cms[col + 1];
            float* cc = acc[mi][nj];
            __half2 h0 = __floats2half2_rn((rm0 && cm0) ? __expf(cc[0] * temp) : 0.f,
                                           (rm0 && cm1) ? __expf(cc[1] * temp) : 0.f);
            __half2 h1 = __floats2half2_rn((rm1 && cm0) ? __expf(cc[2] * temp) : 0.f,
                                           (rm1 && cm1) ? __expf(cc[3] * temp) : 0.f);
            *(__half2*)(e0 + col) = h0;
            *(__half2*)(e0 + (size_t)8 * LL + col) = h1;
        }
    }
}

// ---------------- K2: deterministic row / col sums of E --------------------
__global__ __launch_bounds__(256) void k2_row() {
    const int row = blockIdx.x * 8 + (threadIdx.x >> 5);
    const int lane = threadIdx.x & 31;
    const uint4* p = (const uint4*)(g_E16 + (size_t)row * LL);
    float s = 0.f;
#pragma unroll
    for (int q = 0; q < 4; q++) {
        uint4 v = p[lane + 32 * q];
        const __half2* h = (const __half2*)&v;
#pragma unroll
        for (int i = 0; i < 4; i++) {
            float2 f = __half22float2(h[i]);
            s += f.x + f.y;
        }
    }
#pragma unroll
    for (int o = 16; o > 0; o >>= 1) s += __shfl_xor_sync(0xffffffffu, s, o);
    if (lane == 0) g_R[row] = s;
}

__global__ __launch_bounds__(256) void k2_col() {
    const int batch = blockIdx.y;
    const int col2 = blockIdx.x * 256 + threadIdx.x;   // half2 column index
    const __half2* p = (const __half2*)(g_E16 + (size_t)batch * LL * LL) + col2;
    float sx0 = 0.f, sy0 = 0.f, sx1 = 0.f, sy1 = 0.f;
#pragma unroll 8
    for (int l = 0; l < LL; l += 2) {
        float2 f0 = __half22float2(p[(size_t)l * 512]);
        float2 f1 = __half22float2(p[(size_t)(l + 1) * 512]);
        sx0 += f0.x; sy0 += f0.y; sx1 += f1.x; sy1 += f1.y;
    }
    g_C[batch * LL + 2 * col2]     = sx0 + sx1;
    g_C[batch * LL + 2 * col2 + 1] = sy0 + sy1;
}

// ---------------- K3: dual feature GEMMs (HMMA) ----------------------------
__global__ __launch_bounds__(256) void k3_feat(float* __restrict__ out) {
    extern __shared__ char dsm[];
    __half* Es = (__half*)dsm;            // 128 x SK
    __half* Wb = Es + 128 * SK;
    __half* Wa = Wb + 128 * SK;
    float* smeanb = (float*)(Wa + 128 * SK);
    float* svmask = smeanb + 128;

    const int batch = blockIdx.y, l0 = blockIdx.x * 128;
    const int t = threadIdx.x, lane = t & 31, w = t >> 5;
    const int wr = w >> 2, wc = w & 3;

    if (t < 128) smeanb[t] = g_meanb[batch * HH + t];
    else         svmask[t - 128] = g_vmask[batch * HH + (t - 128)];

    float acc_a[4][4][4], acc_b[4][4][4];
#pragma unroll
    for (int i = 0; i < 4; i++)
#pragma unroll
        for (int j = 0; j < 4; j++)
#pragma unroll
            for (int k = 0; k < 4; k++) { acc_a[i][j][k] = 0.f; acc_b[i][j][k] = 0.f; }

    const int row = t >> 1, kh = (t & 1) * 64;
    const uint32_t eaddr = smem_u32(Es) + ((wr * 64 + (lane & 15)) * SK + (lane >> 4) * 8) * 2;
    const uint32_t baddr = smem_u32(Wb) + ((wc * 32 + (lane & 15)) * SK + (lane >> 4) * 8) * 2;
    const uint32_t aaddr = smem_u32(Wa) + ((wc * 32 + (lane & 15)) * SK + (lane >> 4) * 8) * 2;

    for (int mc = 0; mc < 8; mc++) {
        if (mc) __syncthreads();
        {
            const int m0 = mc * 128;
            const uint4* es = (const uint4*)(g_E16  + ((size_t)(batch * LL + l0 + row)) * LL + m0 + kh);
            const uint4* bs = (const uint4*)(g_b16T + ((size_t)(batch * HH + row)) * LL + m0 + kh);
            const uint4* as = (const uint4*)(g_a16T + ((size_t)(batch * HH + row)) * LL + m0 + kh);
            uint4* ed = (uint4*)(Es + row * SK + kh);
            uint4* bd = (uint4*)(Wb + row * SK + kh);
            uint4* ad = (uint4*)(Wa + row * SK + kh);
#pragma unroll
            for (int j = 0; j < 8; j++) { ed[j] = es[j]; bd[j] = bs[j]; ad[j] = as[j]; }
        }
        __syncthreads();
#pragma unroll
        for (int c = 0; c < 8; c++) {
            uint32_t ev[4][4], bvb[2][4], bva[2][4];
#pragma unroll
            for (int mi = 0; mi < 4; mi++)
                LDSM4(ev[mi][0], ev[mi][1], ev[mi][2], ev[mi][3],
                      eaddr + (mi * 16 * SK + c * 16) * 2);
#pragma unroll
            for (int nh = 0; nh < 2; nh++) {
                LDSM4(bvb[nh][0], bvb[nh][1], bvb[nh][2], bvb[nh][3],
                      baddr + (nh * 16 * SK + c * 16) * 2);
                LDSM4(bva[nh][0], bva[nh][1], bva[nh][2], bva[nh][3],
                      aaddr + (nh * 16 * SK + c * 16) * 2);
            }
#pragma unroll
            for (int mi = 0; mi < 4; mi++)
#pragma unroll
                for (int nj = 0; nj < 4; nj++) {
                    mma_16816(acc_a[mi][nj], ev[mi], bvb[nj >> 1][nj & 1], bvb[nj >> 1][(nj & 1) + 2]);
                    mma_16816(acc_b[mi][nj], ev[mi], bva[nj >> 1][nj & 1], bva[nj >> 1][(nj & 1) + 2]);
                }
        }
    }

    const size_t FB = (size_t)BB * LL * HH;
    const float INV = 1.f / 1024.f;
#pragma unroll
    for (int mi = 0; mi < 4; mi++) {
        const int r0 = wr * 64 + mi * 16 + (lane >> 2);
        const int g0 = batch * LL + l0 + r0;
        const float rv0 = g_R[g0], rv1 = g_R[g0 + 8];
        const float sc0 = (rv0 > 0.f) ? (1.f / rv0) : 0.f;
        const float sc1 = (rv1 > 0.f) ? (1.f / rv1) : 0.f;
        const bool u0 = !(rv0 > 0.f), u1 = !(rv1 > 0.f);
        float* oa0 = out + (size_t)g0 * HH;
        float* oa1 = oa0 + (size_t)8 * HH;
        float* ob0 = oa0 + FB;
        float* ob1 = oa1 + FB;
#pragma unroll
        for (int nj = 0; nj < 4; nj++) {
            const int col = wc * 32 + nj * 8 + (lane & 3) * 2;
            const float mb0 = smeanb[col] * INV, mb1 = smeanb[col + 1] * INV;
            const float vm0 = svmask[col] * INV, vm1 = svmask[col + 1] * INV;
            float* ca = acc_a[mi][nj];
            float* cb = acc_b[mi][nj];
            float2 va0 = { u0 ? mb0 : ca[0] * sc0, u0 ? mb1 : ca[1] * sc0 };
            float2 va1 = { u1 ? mb0 : ca[2] * sc1, u1 ? mb1 : ca[3] * sc1 };
            float2 vb0 = { cb[0] + vm0, cb[1] + vm1 };
            float2 vb1 = { cb[2] + vm0, cb[3] + vm1 };
            *(float2*)(oa0 + col) = va0;
            *(float2*)(oa1 + col) = va1;
            *(float2*)(ob0 + col) = vb0;
            *(float2*)(ob1 + col) = vb1;
        }
    }
}

// ---------------- launch ----------------------------------------------------
extern "C" void kernel_launch(void* const* d_in, const int* in_sizes, int n_in,
                              void* d_out, int out_size) {
    const float* a    = (const float*)d_in[0];
    const float* b    = (const float*)d_in[1];
    const int*   ma   = (const int*)d_in[2];
    const int*   mb   = (const int*)d_in[3];
    const float* temp = (const float*)d_in[4];
    float* out = (float*)d_out;

    const int K1_SMEM = 2 * 128 * SK * 2 + 512;          // 70144
    const int K3_SMEM = 3 * 128 * SK * 2 + 1024;         // 105472
    cudaFuncSetAttribute(k1_scores, cudaFuncAttributeMaxDynamicSharedMemorySize, K1_SMEM);
    cudaFuncSetAttribute(k3_feat,   cudaFuncAttributeMaxDynamicSharedMemorySize, K3_SMEM);

    conv_ab<<<4096, 256>>>(a, b);
    transpose_b<<<dim3(8, BB), 256>>>(b);
    k1_scores<<<dim3(8, 8, BB), 256, K1_SMEM>>>(ma, mb, temp);
    k2_row<<<4096, 256>>>();
    k2_col<<<dim3(2, BB), 256>>>();
    prep_fb<<<dim3(8, BB), 256>>>(a);
    meanb_vmask<<<BB, 256>>>();
    k3_feat<<<dim3(8, BB), 256, K3_SMEM>>>(out);
}

// round 4
// speedup vs baseline: 3.0995x; 1.4620x over previous
#include <cuda_runtime.h>
#include <cuda_fp16.h>
#include <cstdint>

#define BB 32
#define LL 1024
#define HH 128
#define SK 136          // smem row stride in halfs (conflict-free ldmatrix)

// ---------------- scratch (__device__ globals) ------------------------------
__device__ __half g_E16[(size_t)BB * LL * LL];   // exp(masked scores), 64 MB
__device__ __half g_a16[(size_t)BB * LL * HH];   // fp16 a, [b,l,h]
__device__ __half g_b16[(size_t)BB * LL * HH];   // fp16 b, [b,m,h]
__device__ __half g_bT16[(size_t)BB * HH * LL];  // fp16 b transposed [b,d,m]
__device__ __half g_aT16[(size_t)BB * HH * LL];  // fp16 a transposed [b,d,m]
__device__ __half g_aTs16[(size_t)BB * HH * LL]; // fp16 (a*invC)^T [b,d,m]
__device__ float  g_Rp[8][BB * LL];              // per-m-tile partial row sums
__device__ float  g_Cp[8][BB * LL];              // per-l-tile partial col sums
__device__ float  g_R[BB * LL];
__device__ float  g_C[BB * LL];
__device__ float  g_meanb[BB * HH];
__device__ float  g_vmask[BB * HH];

// ---------------- PTX helpers ----------------------------------------------
__device__ __forceinline__ uint32_t smem_u32(const void* p) {
    uint32_t a;
    asm("{ .reg .u64 t; cvta.to.shared.u64 t, %1; cvt.u32.u64 %0, t; }"
        : "=r"(a) : "l"(p));
    return a;
}
#define LDSM4(R0, R1, R2, R3, ADDR)                                            \
    asm volatile("ldmatrix.sync.aligned.m8n8.x4.shared.b16 {%0,%1,%2,%3}, [%4];" \
                 : "=r"(R0), "=r"(R1), "=r"(R2), "=r"(R3) : "r"(ADDR))
#define CP_ASYNC16(DST, SRC)                                                   \
    asm volatile("cp.async.cg.shared.global [%0], [%1], 16;" :: "r"(DST), "l"(SRC))
#define CP_COMMIT() asm volatile("cp.async.commit_group;")
#define CP_WAIT1()  asm volatile("cp.async.wait_group 1;")
#define CP_WAIT0()  asm volatile("cp.async.wait_group 0;")

__device__ __forceinline__ void mma_16816(float* c, const uint32_t* a,
                                          uint32_t b0, uint32_t b1) {
    asm volatile(
        "mma.sync.aligned.m16n8k16.row.col.f32.f16.f16.f32 "
        "{%0,%1,%2,%3},{%4,%5,%6,%7},{%8,%9},{%0,%1,%2,%3};"
        : "+f"(c[0]), "+f"(c[1]), "+f"(c[2]), "+f"(c[3])
        : "r"(a[0]), "r"(a[1]), "r"(a[2]), "r"(a[3]), "r"(b0), "r"(b1));
}

// ---------------- conv_all: fp32 a,b -> fp16 natural + transposed ----------
__global__ __launch_bounds__(256) void conv_all(const float* __restrict__ a,
                                                const float* __restrict__ b) {
    extern __shared__ char dsm[];
    __half* ta = (__half*)dsm;            // 128 x SK
    __half* tb = ta + 128 * SK;
    const int mt = blockIdx.x * 128, batch = blockIdx.y;
    const int t = threadIdx.x;
    const int r = t >> 1, dh = (t & 1) * 64;
    const size_t grow = (size_t)(batch * LL + mt + r) * HH + dh;
    const float4* as = (const float4*)(a + grow);
    const float4* bs = (const float4*)(b + grow);
    uint4 abuf[8], bbuf[8];
#pragma unroll
    for (int j = 0; j < 8; j++) {
        float4 va0 = as[2 * j], va1 = as[2 * j + 1];
        float4 vb0 = bs[2 * j], vb1 = bs[2 * j + 1];
        uint4 pa, pb;
        ((__half2*)&pa)[0] = __floats2half2_rn(va0.x, va0.y);
        ((__half2*)&pa)[1] = __floats2half2_rn(va0.z, va0.w);
        ((__half2*)&pa)[2] = __floats2half2_rn(va1.x, va1.y);
        ((__half2*)&pa)[3] = __floats2half2_rn(va1.z, va1.w);
        ((__half2*)&pb)[0] = __floats2half2_rn(vb0.x, vb0.y);
        ((__half2*)&pb)[1] = __floats2half2_rn(vb0.z, vb0.w);
        ((__half2*)&pb)[2] = __floats2half2_rn(vb1.x, vb1.y);
        ((__half2*)&pb)[3] = __floats2half2_rn(vb1.z, vb1.w);
        abuf[j] = pa; bbuf[j] = pb;
        ((uint4*)(g_a16 + grow))[j] = pa;
        ((uint4*)(g_b16 + grow))[j] = pb;
    }
    // scatter into smem transpose tiles
#pragma unroll
    for (int j = 0; j < 8; j++) {
        const __half* ha = (const __half*)&abuf[j];
        const __half* hb = (const __half*)&bbuf[j];
#pragma unroll
        for (int k = 0; k < 8; k++) {
            ta[(dh + j * 8 + k) * SK + r] = ha[k];
            tb[(dh + j * 8 + k) * SK + r] = hb[k];
        }
    }
    __syncthreads();
    const int d = t >> 1, mh = (t & 1) * 64;
    const size_t trow = (size_t)(batch * HH + d) * LL + mt + mh;
    const uint4* sa = (const uint4*)(ta + d * SK + mh);
    const uint4* sb = (const uint4*)(tb + d * SK + mh);
#pragma unroll
    for (int q = 0; q < 8; q++) {
        ((uint4*)(g_aT16 + trow))[q] = sa[q];
        ((uint4*)(g_bT16 + trow))[q] = sb[q];
    }
}

// ---------------- K1: HMMA scores + mask + exp + fused partial sums --------
__global__ __launch_bounds__(256) void k1_scores(const int* __restrict__ ma,
                                                 const int* __restrict__ mb,
                                                 const float* __restrict__ tptr) {
    extern __shared__ char dsm[];
    __half* As = (__half*)dsm;            // 128 x SK
    __half* Bs = As + 128 * SK;
    int*   cms = (int*)(Bs + 128 * SK);   // 128 ints
    float* rs  = (float*)(cms + 128);     // [4][128]
    float* cs  = rs + 4 * 128;            // [2][128]

    const int batch = blockIdx.z, l0 = blockIdx.y * 128, m0 = blockIdx.x * 128;
    const int t = threadIdx.x, lane = t & 31, w = t >> 5;
    const int wr = w >> 2, wc = w & 3;

    if (t < 128) cms[t] = mb[batch * LL + m0 + t];
    {
        const int row = t >> 1, kh = (t & 1) * 64;
        const uint4* asrc = (const uint4*)(g_a16 + ((size_t)(batch * LL + l0 + row)) * HH + kh);
        const uint4* bsrc = (const uint4*)(g_b16 + ((size_t)(batch * LL + m0 + row)) * HH + kh);
        uint4* adst = (uint4*)(As + row * SK + kh);
        uint4* bdst = (uint4*)(Bs + row * SK + kh);
#pragma unroll
        for (int j = 0; j < 8; j++) { adst[j] = asrc[j]; bdst[j] = bsrc[j]; }
    }
    __syncthreads();

    float acc[4][4][4];
#pragma unroll
    for (int i = 0; i < 4; i++)
#pragma unroll
        for (int j = 0; j < 4; j++)
#pragma unroll
            for (int k = 0; k < 4; k++) acc[i][j][k] = 0.f;

    const uint32_t aaddr = smem_u32(As) + ((wr * 64 + (lane & 15)) * SK + (lane >> 4) * 8) * 2;
    const uint32_t baddr = smem_u32(Bs) + ((wc * 32 + (lane & 15)) * SK + (lane >> 4) * 8) * 2;
#pragma unroll
    for (int c = 0; c < 8; c++) {
        uint32_t av[4][4], bv[2][4];
#pragma unroll
        for (int mi = 0; mi < 4; mi++)
            LDSM4(av[mi][0], av[mi][1], av[mi][2], av[mi][3],
                  aaddr + (mi * 16 * SK + c * 16) * 2);
#pragma unroll
        for (int nh = 0; nh < 2; nh++)
            LDSM4(bv[nh][0], bv[nh][1], bv[nh][2], bv[nh][3],
                  baddr + (nh * 16 * SK + c * 16) * 2);
#pragma unroll
        for (int mi = 0; mi < 4; mi++)
#pragma unroll
            for (int nj = 0; nj < 4; nj++)
                mma_16816(acc[mi][nj], av[mi], bv[nj >> 1][nj & 1], bv[nj >> 1][(nj & 1) + 2]);
    }

    const float temp = *tptr;
    float cloc[4][2];
#pragma unroll
    for (int nj = 0; nj < 4; nj++) { cloc[nj][0] = 0.f; cloc[nj][1] = 0.f; }

#pragma unroll
    for (int mi = 0; mi < 4; mi++) {
        const int r0 = wr * 64 + mi * 16 + (lane >> 2);
        const int gr0 = batch * LL + l0 + r0;
        const int rm0 = ma[gr0], rm1 = ma[gr0 + 8];
        __half* e0 = g_E16 + (size_t)gr0 * LL + m0;
        float r0sum = 0.f, r1sum = 0.f;
#pragma unroll
        for (int nj = 0; nj < 4; nj++) {
            const int col = wc * 32 + nj * 8 + (lane & 3) * 2;
            const int cm0 = cms[col], cm1 = cms[col + 1];
            float* cc = acc[mi][nj];
            const float v00 = (rm0 && cm0) ? __expf(cc[0] * temp) : 0.f;
            const float v01 = (rm0 && cm1) ? __expf(cc[1] * temp) : 0.f;
            const float v10 = (rm1 && cm0) ? __expf(cc[2] * temp) : 0.f;
            const float v11 = (rm1 && cm1) ? __expf(cc[3] * temp) : 0.f;
            *(__half2*)(e0 + col) = __floats2half2_rn(v00, v01);
            *(__half2*)(e0 + (size_t)8 * LL + col) = __floats2half2_rn(v10, v11);
            r0sum += v00 + v01; r1sum += v10 + v11;
            cloc[nj][0] += v00 + v10; cloc[nj][1] += v01 + v11;
        }
        // reduce rows over the 4 column-lanes (lane&3)
        r0sum += __shfl_xor_sync(0xffffffffu, r0sum, 1);
        r0sum += __shfl_xor_sync(0xffffffffu, r0sum, 2);
        r1sum += __shfl_xor_sync(0xffffffffu, r1sum, 1);
        r1sum += __shfl_xor_sync(0xffffffffu, r1sum, 2);
        if ((lane & 3) == 0) {
            rs[wc * 128 + r0] = r0sum;
            rs[wc * 128 + r0 + 8] = r1sum;
        }
    }
    // reduce cols over the 8 row-lanes (lane>>2)
#pragma unroll
    for (int nj = 0; nj < 4; nj++)
#pragma unroll
        for (int k = 0; k < 2; k++) {
            float v = cloc[nj][k];
            v += __shfl_xor_sync(0xffffffffu, v, 4);
            v += __shfl_xor_sync(0xffffffffu, v, 8);
            v += __shfl_xor_sync(0xffffffffu, v, 16);
            if (lane < 4) cs[wr * 128 + wc * 32 + nj * 8 + lane * 2 + k] = v;
        }
    __syncthreads();
    if (t < 128) {
        g_Rp[blockIdx.x][batch * LL + l0 + t] =
            rs[t] + rs[128 + t] + rs[256 + t] + rs[384 + t];
        g_Cp[blockIdx.y][batch * LL + m0 + t] = cs[t] + cs[128 + t];
    }
}

// ---------------- reduce partial sums --------------------------------------
__global__ __launch_bounds__(256) void reduce_RC() {
    const int idx = blockIdx.x * 256 + threadIdx.x;
    if (idx < BB * LL) {
        float s = 0.f;
#pragma unroll
        for (int q = 0; q < 8; q++) s += g_Rp[q][idx];
        g_R[idx] = s;
    } else {
        const int i = idx - BB * LL;
        float s = 0.f;
#pragma unroll
        for (int q = 0; q < 8; q++) s += g_Cp[q][i];
        g_C[i] = s;
    }
}

// ---------------- prep_fb: aTs[d][m] = aT[d][m] * invC[m] ------------------
__global__ __launch_bounds__(256) void prep_fb() {
    __shared__ float sc[128];
    const int mt = blockIdx.x * 128, batch = blockIdx.y;
    const int t = threadIdx.x;
    if (t < 128) {
        const float cv = g_C[batch * LL + mt + t];
        sc[t] = (cv > 0.f) ? (1.f / cv) : 0.f;
    }
    __syncthreads();
    const int d = t >> 1, mh = (t & 1) * 64;
    const size_t trow = (size_t)(batch * HH + d) * LL + mt + mh;
    const uint4* src = (const uint4*)(g_aT16 + trow);
    uint4* dst = (uint4*)(g_aTs16 + trow);
#pragma unroll
    for (int q = 0; q < 8; q++) {
        uint4 v = src[q];
        __half2* h = (__half2*)&v;
#pragma unroll
        for (int k = 0; k < 4; k++) {
            float2 f = __half22float2(h[k]);
            const int ml = mh + q * 8 + k * 2;
            f.x *= sc[ml]; f.y *= sc[ml + 1];
            h[k] = __floats2half2_rn(f.x, f.y);
        }
        dst[q] = v;
    }
}

// ---------------- meanb / vmask (coalesced over transposed rows) -----------
__global__ __launch_bounds__(256) void meanb_vmask() {
    const int batch = blockIdx.y;
    const int d = blockIdx.x * 8 + (threadIdx.x >> 5);
    const int lane = threadIdx.x & 31;
    const uint4* bp = (const uint4*)(g_bT16 + (size_t)(batch * HH + d) * LL);
    const uint4* ap = (const uint4*)(g_aT16 + (size_t)(batch * HH + d) * LL);
    const float* cp = g_C + batch * LL;
    float sb = 0.f, sv = 0.f;
#pragma unroll
    for (int q = 0; q < 4; q++) {
        const int ci = lane + 32 * q;
        uint4 vb = bp[ci];
        uint4 va = ap[ci];
        const __half2* hb = (const __half2*)&vb;
        const __half2* ha = (const __half2*)&va;
        const float4* c4 = (const float4*)(cp + ci * 8);
        float4 c0 = c4[0], c1 = c4[1];
        const float* cw = (const float*)&c0;
        const float* cw1 = (const float*)&c1;
#pragma unroll
        for (int k = 0; k < 2; k++) {
            float2 fb = __half22float2(hb[k]);
            float2 fa = __half22float2(ha[k]);
            sb += fb.x + fb.y;
            sv += (cw[2 * k] > 0.f ? 0.f : fa.x) + (cw[2 * k + 1] > 0.f ? 0.f : fa.y);
        }
#pragma unroll
        for (int k = 0; k < 2; k++) {
            float2 fb = __half22float2(hb[k + 2]);
            float2 fa = __half22float2(ha[k + 2]);
            sb += fb.x + fb.y;
            sv += (cw1[2 * k] > 0.f ? 0.f : fa.x) + (cw1[2 * k + 1] > 0.f ? 0.f : fa.y);
        }
    }
#pragma unroll
    for (int o = 16; o > 0; o >>= 1) {
        sb += __shfl_xor_sync(0xffffffffu, sb, o);
        sv += __shfl_xor_sync(0xffffffffu, sv, o);
    }
    if (lane == 0) {
        g_meanb[batch * HH + d] = sb;
        g_vmask[batch * HH + d] = sv;
    }
}

// ---------------- K3: dual feature GEMMs, cp.async double-buffered ---------
#define SSTRIDE (3 * 128 * SK)      // halfs per stage

__global__ __launch_bounds__(256) void k3_feat(float* __restrict__ out) {
    extern __shared__ char dsm[];
    __half* S = (__half*)dsm;                       // 2 stages x (Es|Wb|Wa)
    float* smeanb = (float*)(S + 2 * SSTRIDE);
    float* svmask = smeanb + 128;

    const int batch = blockIdx.y, l0 = blockIdx.x * 128;
    const int t = threadIdx.x, lane = t & 31, w = t >> 5;
    const int wr = w >> 2, wc = w & 3;
    const uint32_t sbase = smem_u32(S);

    if (t < 128) smeanb[t] = g_meanb[batch * HH + t];
    else         svmask[t - 128] = g_vmask[batch * HH + (t - 128)];

    const int row = t >> 1, kh = (t & 1) * 64;
    const __half* eg = g_E16   + ((size_t)(batch * LL + l0 + row)) * LL + kh;
    const __half* bg = g_bT16  + ((size_t)(batch * HH + row)) * LL + kh;
    const __half* ag = g_aTs16 + ((size_t)(batch * HH + row)) * LL + kh;
    const uint32_t sdst = sbase + (row * SK + kh) * 2;

    // prefetch stage 0 (mc = 0)
    {
#pragma unroll
        for (int j = 0; j < 8; j++) {
            CP_ASYNC16(sdst + j * 16,                    eg + j * 8);
            CP_ASYNC16(sdst + 128 * SK * 2 + j * 16,     bg + j * 8);
            CP_ASYNC16(sdst + 256 * SK * 2 + j * 16,     ag + j * 8);
        }
        CP_COMMIT();
    }

    float acc_a[4][4][4], acc_b[4][4][4];
#pragma unroll
    for (int i = 0; i < 4; i++)
#pragma unroll
        for (int j = 0; j < 4; j++)
#pragma unroll
            for (int k = 0; k < 4; k++) { acc_a[i][j][k] = 0.f; acc_b[i][j][k] = 0.f; }

    const uint32_t eoff = sbase + ((wr * 64 + (lane & 15)) * SK + (lane >> 4) * 8) * 2;
    const uint32_t woff = sbase + ((wc * 32 + (lane & 15)) * SK + (lane >> 4) * 8) * 2;

    for (int mc = 0; mc < 8; mc++) {
        if (mc < 7) {
            const uint32_t nb = ((mc + 1) & 1) * SSTRIDE * 2;
            const int m1 = (mc + 1) * 128;
#pragma unroll
            for (int j = 0; j < 8; j++) {
                CP_ASYNC16(sdst + nb + j * 16,                eg + m1 + j * 8);
                CP_ASYNC16(sdst + nb + 128 * SK * 2 + j * 16, bg + m1 + j * 8);
                CP_ASYNC16(sdst + nb + 256 * SK * 2 + j * 16, ag + m1 + j * 8);
            }
            CP_COMMIT();
            CP_WAIT1();
        } else {
            CP_WAIT0();
        }
        __syncthreads();

        const uint32_t sb_ = (mc & 1) * SSTRIDE * 2;
        const uint32_t eaddr = eoff + sb_;
        const uint32_t baddr = woff + sb_ + 128 * SK * 2;
        const uint32_t aaddr = woff + sb_ + 256 * SK * 2;
#pragma unroll
        for (int c = 0; c < 8; c++) {
            uint32_t ev[4][4], bvb[2][4], bva[2][4];
#pragma unroll
            for (int mi = 0; mi < 4; mi++)
                LDSM4(ev[mi][0], ev[mi][1], ev[mi][2], ev[mi][3],
                      eaddr + (mi * 16 * SK + c * 16) * 2);
#pragma unroll
            for (int nh = 0; nh < 2; nh++) {
                LDSM4(bvb[nh][0], bvb[nh][1], bvb[nh][2], bvb[nh][3],
                      baddr + (nh * 16 * SK + c * 16) * 2);
                LDSM4(bva[nh][0], bva[nh][1], bva[nh][2], bva[nh][3],
                      aaddr + (nh * 16 * SK + c * 16) * 2);
            }
#pragma unroll
            for (int mi = 0; mi < 4; mi++)
#pragma unroll
                for (int nj = 0; nj < 4; nj++) {
                    mma_16816(acc_a[mi][nj], ev[mi], bvb[nj >> 1][nj & 1], bvb[nj >> 1][(nj & 1) + 2]);
                    mma_16816(acc_b[mi][nj], ev[mi], bva[nj >> 1][nj & 1], bva[nj >> 1][(nj & 1) + 2]);
                }
        }
        __syncthreads();
    }

    const size_t FB = (size_t)BB * LL * HH;
    const float INV = 1.f / 1024.f;
#pragma unroll
    for (int mi = 0; mi < 4; mi++) {
        const int r0 = wr * 64 + mi * 16 + (lane >> 2);
        const int g0 = batch * LL + l0 + r0;
        const float rv0 = g_R[g0], rv1 = g_R[g0 + 8];
        const float sc0 = (rv0 > 0.f) ? (1.f / rv0) : 0.f;
        const float sc1 = (rv1 > 0.f) ? (1.f / rv1) : 0.f;
        const bool u0 = !(rv0 > 0.f), u1 = !(rv1 > 0.f);
        float* oa0 = out + (size_t)g0 * HH;
        float* oa1 = oa0 + (size_t)8 * HH;
        float* ob0 = oa0 + FB;
        float* ob1 = oa1 + FB;
#pragma unroll
        for (int nj = 0; nj < 4; nj++) {
            const int col = wc * 32 + nj * 8 + (lane & 3) * 2;
            const float mb0 = smeanb[col] * INV, mb1 = smeanb[col + 1] * INV;
            const float vm0 = svmask[col] * INV, vm1 = svmask[col + 1] * INV;
            float* ca = acc_a[mi][nj];
            float* cb = acc_b[mi][nj];
            float2 va0 = { u0 ? mb0 : ca[0] * sc0, u0 ? mb1 : ca[1] * sc0 };
            float2 va1 = { u1 ? mb0 : ca[2] * sc1, u1 ? mb1 : ca[3] * sc1 };
            float2 vb0 = { cb[0] + vm0, cb[1] + vm1 };
            float2 vb1 = { cb[2] + vm0, cb[3] + vm1 };
            *(float2*)(oa0 + col) = va0;
            *(float2*)(oa1 + col) = va1;
            *(float2*)(ob0 + col) = vb0;
            *(float2*)(ob1 + col) = vb1;
        }
    }
}

// ---------------- launch ----------------------------------------------------
extern "C" void kernel_launch(void* const* d_in, const int* in_sizes, int n_in,
                              void* d_out, int out_size) {
    const float* a    = (const float*)d_in[0];
    const float* b    = (const float*)d_in[1];
    const int*   ma   = (const int*)d_in[2];
    const int*   mb   = (const int*)d_in[3];
    const float* temp = (const float*)d_in[4];
    float* out = (float*)d_out;

    const int CV_SMEM = 2 * 128 * SK * 2;                    // 69632
    const int K1_SMEM = 2 * 128 * SK * 2 + 512 + 2048 + 1024;// 73216
    const int K3_SMEM = 2 * SSTRIDE * 2 + 1024;              // 209920
    cudaFuncSetAttribute(conv_all,  cudaFuncAttributeMaxDynamicSharedMemorySize, CV_SMEM);
    cudaFuncSetAttribute(k1_scores, cudaFuncAttributeMaxDynamicSharedMemorySize, K1_SMEM);
    cudaFuncSetAttribute(k3_feat,   cudaFuncAttributeMaxDynamicSharedMemorySize, K3_SMEM);

    conv_all<<<dim3(8, BB), 256, CV_SMEM>>>(a, b);
    k1_scores<<<dim3(8, 8, BB), 256, K1_SMEM>>>(ma, mb, temp);
    reduce_RC<<<256, 256>>>();
    prep_fb<<<dim3(8, BB), 256>>>();
    meanb_vmask<<<dim3(16, BB), 256>>>();
    k3_feat<<<dim3(8, BB), 256, K3_SMEM>>>(out);
}